// round 11
// baseline (speedup 1.0000x reference)
#include <cuda_runtime.h>

// Problem constants (from reference)
#define VOCAB   512
#define MAXLEN  512
#define BATCH   128
#define NFEAT   (VOCAB + VOCAB * VOCAB + 2)   // 262658

// One CTA per batch row, 512 threads, one position per thread.
// R10 mechanism kept: W gathers issued UNCONDITIONALLY (indices always valid:
// unigram < 512, bigram <= 262655 < NFEAT-2), length mask applied after the
// loads return, so lengths no longer gates the gather chain.
// R11 tail: producer warps (1..15) bar.arrive and retire; consumer warp 0
// bar.syncs and finishes. Epilogue scalars prefetched before the barrier so
// their latency overlaps stage 1 + barrier.
__global__ __launch_bounds__(512, 2)
void lr_ngram_kernel(const float* __restrict__ x,
                     const int*   __restrict__ lengths,
                     const float* __restrict__ W,
                     const float* __restrict__ bias,
                     float*       __restrict__ out)
{
    __shared__ float s_sum[16];
    __shared__ float s_max[16];

    const int b    = blockIdx.x;
    const int j    = threadIdx.x;          // position, 0..511
    const int lane = j & 31;
    const int wid  = j >> 5;

    const float* __restrict__ xr = x + (size_t)b * MAXLEN * 2;

    // Independent loads, all issued up front: x pair, neighbor action,
    // lengths (does not gate the gathers).
    const int jn = (j + 1 < MAXLEN) ? j + 1 : j;
    float2 at  = reinterpret_cast<const float2*>(xr)[j];     // (a_j, t_j)
    float  anf = __ldg(&xr[jn * 2]);                         // a_{j+1}
    const int len = __ldg(&lengths[b]);

    int a  = (int)at.x;
    int an = (int)anf;

    // Unconditional gathers; mask afterwards.
    float wu = W[a];                                // unigram weight
    float wb = W[VOCAB + (a << 9) + an];            // bigram weight

    // Warp 0: prefetch epilogue scalars now — overlaps stage 1 + barrier.
    float w_time = 0.0f, w_cnt = 0.0f, bs = 0.0f;
    if (wid == 0) {
        w_time = __ldg(&W[NFEAT - 2]);
        w_cnt  = __ldg(&W[NFEAT - 1]);
        bs     = __ldg(&bias[0]);
    }

    float sum = ((j     < len) ? wu : 0.0f)
              + ((j + 1 < len) ? wb : 0.0f);
    float tmax = (j < len) ? at.y : -3.402823466e38f;

    // Stage 1: warp reduction (sum + max together).
    const unsigned m = 0xffffffffu;
    #pragma unroll
    for (int off = 16; off > 0; off >>= 1) {
        sum  += __shfl_down_sync(m, sum, off);
        tmax  = fmaxf(tmax, __shfl_down_sync(m, tmax, off));
    }
    if (lane == 0) { s_sum[wid] = sum; s_max[wid] = tmax; }

    // Producer warps arrive (non-blocking) and retire; warp 0 waits.
    if (wid != 0) {
        asm volatile("bar.arrive 1, %0;" :: "r"(512) : "memory");
        return;
    }
    asm volatile("bar.sync 1, %0;" :: "r"(512) : "memory");

    // Stage 2: 16 partials reduced by warp 0.
    sum  = (lane < 16) ? s_sum[lane] : 0.0f;
    tmax = (lane < 16) ? s_max[lane] : -3.402823466e38f;
    #pragma unroll
    for (int off = 8; off > 0; off >>= 1) {
        sum  += __shfl_down_sync(m, sum, off);
        tmax  = fmaxf(tmax, __shfl_down_sync(m, tmax, off));
    }
    if (lane == 0) {
        out[b] = sum + tmax * w_time + (float)len * w_cnt + bs;
    }
}

extern "C" void kernel_launch(void* const* d_in, const int* in_sizes, int n_in,
                              void* d_out, int out_size)
{
    const float* x       = (const float*)d_in[0];   // [B, MAXLEN, 2] f32
    const int*   lengths = (const int*)  d_in[1];   // [B] i32
    const float* W       = (const float*)d_in[2];   // [1, F] f32
    const float* bias    = (const float*)d_in[3];   // [1] f32
    float*       out     = (float*)d_out;           // [B, 1] f32

    lr_ngram_kernel<<<BATCH, 512>>>(x, lengths, W, bias, out);
}